// round 2
// baseline (speedup 1.0000x reference)
#include <cuda_runtime.h>
#include <math.h>

// ElasticBand (NEB) — fused persistent kernel with software grid barrier.
// Per interior image i:
//   phase 1: stream pos[i+1], frc[i]; accumulate 6 per-image dot products
//            (A=dp.dp, B=dm.dm, C=dp.dm, D=f.dp, E=f.dm, W=f.f); block partial -> L2
//   grid barrier (monotonic counter)
//   phase 2: every block folds partials (deterministic), computes scalar coeffs
//            (g1, alpha, beta), writes out[i] = g1*f + alpha*dp + beta*dm from REGISTERS.
// DRAM traffic: pos once, frc once, out once = 3 * 153.6 MB.

#define KMAXC 0.1f
#define DLTKC 0.02f
#define EPSC  0.1f
#define PI_F  3.14159265358979323846f

#define TF    1024    // threads, fused kernel
#define KPTF  2       // float4 per thread
#define MAX_INT 62
#define MAX_G   512   // fused partial blocks
#define MAX_NB  1280  // fallback partial blocks

__device__ float g_part[(size_t)MAX_INT * MAX_NB * 6];
__device__ float g_escal[MAX_INT * 6];   // cp, cm, km, kp, mult, pad
__device__ float g_coef[MAX_INT * 4];    // fallback path
__device__ unsigned int g_arrive;

__device__ __forceinline__ float warpSum(float v) {
    #pragma unroll
    for (int o = 16; o > 0; o >>= 1) v += __shfl_xor_sync(0xffffffffu, v, o);
    return v;
}

__device__ __forceinline__ float spring_k(float ea, float eb, float emax, float eref) {
    float ei = fmaxf(ea, eb);
    float k = KMAXC - DLTKC * (emax - ei) / (emax - eref);
    if (ei < eref) k = KMAXC - DLTKC;
    return k;
}

// ---- eng-only precompute + barrier reset (1 tiny block) --------------------
__global__ void nebInit(const float* __restrict__ eng, int n_img)
{
    if (threadIdx.x != 0) return;
    g_arrive = 0u;

    float emin = eng[0], emax = eng[0];
    int imax = 0;
    for (int p = 1; p < n_img; p++) {
        float e = eng[p];
        if (e < emin) emin = e;
        if (e > emax) { emax = e; imax = p; }
    }
    const float eref = emin - EPSC;
    const int n_int = n_img - 2;

    for (int j = 0; j < n_int; j++) {
        const int i = j + 1;
        const float e0 = eng[i - 1], e1 = eng[i], e2 = eng[i + 1];
        const float km = spring_k(e0, e1, emax, eref);
        const float kp = spring_k(e1, e2, emax, eref);

        float cp, cm;
        if (e2 > e1 && e1 > e0)      { cp = 1.f;  cm = 0.f; }
        else if (e2 < e1 && e1 < e0) { cp = 0.f;  cm = 1.f; }
        else {
            float d1 = fabsf(e2 - e1), d0 = fabsf(e0 - e1);
            float dvmax = fmaxf(d1, d0), dvmin = fminf(d1, d0);
            if (e2 > e1)      { cp = dvmax; cm = dvmin; }
            else if (e2 < e1) { cp = dvmin; cm = dvmax; }
            else              { cp = 0.f;   cm = 0.f; }
        }
        const float mult = (j == imax) ? 2.f : 1.f; // .at[i_raw] on interior array; OOB -> no-op

        g_escal[j * 6 + 0] = cp;
        g_escal[j * 6 + 1] = cm;
        g_escal[j * 6 + 2] = km;
        g_escal[j * 6 + 3] = kp;
        g_escal[j * 6 + 4] = mult;
    }
}

// ---- coefficient math from folded sums -------------------------------------
__device__ __forceinline__ void coefFrom(
    const float* S, int ii, float& g1, float& al, float& be)
{
    const float A = S[0], B = S[1], C = S[2], D = S[3], E = S[4], W = S[5];
    const float cp = g_escal[ii * 6 + 0];
    const float cm = g_escal[ii * 6 + 1];
    const float km = g_escal[ii * 6 + 2];
    const float kp = g_escal[ii * 6 + 3];
    const float mu = g_escal[ii * 6 + 4];

    const float Stt = cp * cp * A + 2.f * cp * cm * C + cm * cm * B;
    const float Sft = cp * D + cm * E;
    const float a   = Sft / Stt;
    const float s   = (kp * sqrtf(B) - km * sqrtf(A)) / sqrtf(Stt);

    const float F   = W - Sft * Sft / Stt;
    const float Tm  = cp * C + cm * B;
    const float Tp  = cp * A + cm * C;
    const float St  = kp * Tm - km * Tp;
    const float Gv  = kp * kp * B + km * km * A - 2.f * kp * km * C
                      - 2.f * s * St + s * s * Stt;
    const float Sf  = kp * E - km * D;
    const float H   = Sf - a * St - s * Sft + s * a * Stt;

    const float sw  = (2.0f / PI_F) * atan2f(F, Gv);
    const float Hsw = H * sw;

    g1 = 1.f - Hsw;
    al = a * (Hsw - mu) * cp - km;
    be = a * (Hsw - mu) * cm + kp;
}

// ---- fused persistent kernel ------------------------------------------------
__global__ void __launch_bounds__(TF, 1) nebFused(
    const float4* __restrict__ pos4,
    const float4* __restrict__ frc4,
    float4* __restrict__ out4,
    int nvec, int n_img, int G)
{
    const int b = blockIdx.x;
    const int t = threadIdx.x;
    const int n_int = n_img - 2;

    int  idx[KPTF];
    bool ok[KPTF];
    float4 pPrev[KPTF], pCur[KPTF], f[KPTF], dp[KPTF];

    #pragma unroll
    for (int k = 0; k < KPTF; k++) {
        int j = b * (TF * KPTF) + k * TF + t;
        idx[k] = j;
        ok[k]  = (j < nvec);
        float4 z = make_float4(0.f, 0.f, 0.f, 0.f);
        pPrev[k] = z; pCur[k] = z; f[k] = z; dp[k] = z;
        if (ok[k]) {
            pPrev[k] = __ldcs(&pos4[j]);                   // pos image 0
            pCur[k]  = __ldcs(&pos4[(size_t)nvec + j]);    // pos image 1
            // out[0] = frc[0]
            float4 f0 = __ldcs(&frc4[j]);
            __stcs(&out4[j], f0);
        }
    }

    __shared__ float sred[6][TF / 32];
    __shared__ float scoef[3];

    unsigned int target = 0;

    for (int ii = 0; ii < n_int; ii++) {
        const int i = ii + 1;

        float vA = 0.f, vB = 0.f, vC = 0.f, vD = 0.f, vE = 0.f, vW = 0.f;

        #pragma unroll
        for (int k = 0; k < KPTF; k++) {
            if (ok[k]) {
                float4 pN = __ldcs(&pos4[(size_t)(i + 1) * nvec + idx[k]]);
                f[k]      = __ldcs(&frc4[(size_t)i * nvec + idx[k]]);

                float dpx = pCur[k].x - pPrev[k].x, dmx = pN.x - pCur[k].x;
                float dpy = pCur[k].y - pPrev[k].y, dmy = pN.y - pCur[k].y;
                float dpz = pCur[k].z - pPrev[k].z, dmz = pN.z - pCur[k].z;
                float dpw = pCur[k].w - pPrev[k].w, dmw = pN.w - pCur[k].w;

                vA = fmaf(dpx, dpx, fmaf(dpy, dpy, fmaf(dpz, dpz, fmaf(dpw, dpw, vA))));
                vB = fmaf(dmx, dmx, fmaf(dmy, dmy, fmaf(dmz, dmz, fmaf(dmw, dmw, vB))));
                vC = fmaf(dpx, dmx, fmaf(dpy, dmy, fmaf(dpz, dmz, fmaf(dpw, dmw, vC))));
                vD = fmaf(f[k].x, dpx, fmaf(f[k].y, dpy, fmaf(f[k].z, dpz, fmaf(f[k].w, dpw, vD))));
                vE = fmaf(f[k].x, dmx, fmaf(f[k].y, dmy, fmaf(f[k].z, dmz, fmaf(f[k].w, dmw, vE))));
                vW = fmaf(f[k].x, f[k].x, fmaf(f[k].y, f[k].y, fmaf(f[k].z, f[k].z, fmaf(f[k].w, f[k].w, vW))));

                dp[k].x = dpx; dp[k].y = dpy; dp[k].z = dpz; dp[k].w = dpw;
                pPrev[k] = pCur[k];
                pCur[k]  = pN;
            }
        }

        // block reduce 6 sums
        float vals[6] = { vA, vB, vC, vD, vE, vW };
        #pragma unroll
        for (int c = 0; c < 6; c++) {
            float r = warpSum(vals[c]);
            if ((t & 31) == 0) sred[c][t >> 5] = r;
        }
        __syncthreads();

        // thread 0: write block partial, release, arrive, spin
        target += (unsigned int)G;
        if (t == 0) {
            #pragma unroll
            for (int c = 0; c < 6; c++) {
                float s = 0.f;
                #pragma unroll
                for (int w = 0; w < TF / 32; w++) s += sred[c][w];
                g_part[((size_t)ii * G + b) * 6 + c] = s;
            }
            __threadfence();
            atomicAdd(&g_arrive, 1u);
            unsigned int v;
            do {
                asm volatile("ld.acquire.gpu.u32 %0, [%1];"
                             : "=r"(v) : "l"(&g_arrive) : "memory");
            } while (v < target);
        }
        __syncthreads();

        // fold partials (every block, deterministic order)
        float facc[6] = {0.f, 0.f, 0.f, 0.f, 0.f, 0.f};
        for (int p = t; p < G; p += TF) {
            #pragma unroll
            for (int c = 0; c < 6; c++)
                facc[c] += g_part[((size_t)ii * G + p) * 6 + c];
        }
        #pragma unroll
        for (int c = 0; c < 6; c++) {
            float r = warpSum(facc[c]);
            if ((t & 31) == 0) sred[c][t >> 5] = r;
        }
        __syncthreads();
        if (t == 0) {
            float S[6];
            #pragma unroll
            for (int c = 0; c < 6; c++) {
                float s = 0.f;
                #pragma unroll
                for (int w = 0; w < TF / 32; w++) s += sred[c][w];
                S[c] = s;
            }
            float g1, al, be;
            coefFrom(S, ii, g1, al, be);
            scoef[0] = g1; scoef[1] = al; scoef[2] = be;
        }
        __syncthreads();

        const float g1 = scoef[0], al = scoef[1], be = scoef[2];

        // out[i] from registers: dm = pCur - pPrev (post-roll = pos[i+1]-pos[i])
        #pragma unroll
        for (int k = 0; k < KPTF; k++) {
            if (ok[k]) {
                float4 o;
                o.x = fmaf(g1, f[k].x, fmaf(al, dp[k].x, be * (pCur[k].x - pPrev[k].x)));
                o.y = fmaf(g1, f[k].y, fmaf(al, dp[k].y, be * (pCur[k].y - pPrev[k].y)));
                o.z = fmaf(g1, f[k].z, fmaf(al, dp[k].z, be * (pCur[k].z - pPrev[k].z)));
                o.w = fmaf(g1, f[k].w, fmaf(al, dp[k].w, be * (pCur[k].w - pPrev[k].w)));
                __stcs(&out4[(size_t)i * nvec + idx[k]], o);
            }
        }
    }

    // out[n_img-1] = frc[n_img-1]
    #pragma unroll
    for (int k = 0; k < KPTF; k++) {
        if (ok[k]) {
            size_t g = (size_t)(n_img - 1) * nvec + idx[k];
            float4 fl = __ldcs(&frc4[g]);
            __stcs(&out4[g], fl);
        }
    }
}

// ======================= Fallback 3-kernel path (round-1) ====================
#define TA  256
#define KPT 2

__global__ void __launch_bounds__(TA) nebReduce(
    const float4* __restrict__ pos4,
    const float4* __restrict__ frc4,
    int nvec, int n_img, int nb)
{
    const int b = blockIdx.x;
    const int t = threadIdx.x;

    int   idx[KPT];
    bool  ok[KPT];
    float4 pPrev[KPT], pCur[KPT];

    #pragma unroll
    for (int k = 0; k < KPT; k++) {
        int j = b * (TA * KPT) + k * TA + t;
        idx[k] = j;
        ok[k]  = (j < nvec);
        if (ok[k]) {
            pPrev[k] = pos4[j];
            pCur[k]  = pos4[(size_t)nvec + j];
        } else {
            pPrev[k] = make_float4(0.f, 0.f, 0.f, 0.f);
            pCur[k]  = make_float4(0.f, 0.f, 0.f, 0.f);
        }
    }

    __shared__ float sred[6][TA / 32];
    const int n_int = n_img - 2;

    for (int ii = 0; ii < n_int; ii++) {
        const int i = ii + 1;
        float vA = 0.f, vB = 0.f, vC = 0.f, vD = 0.f, vE = 0.f, vW = 0.f;

        #pragma unroll
        for (int k = 0; k < KPT; k++) {
            if (ok[k]) {
                float4 pN = pos4[(size_t)(i + 1) * nvec + idx[k]];
                float4 fv = frc4[(size_t)i * nvec + idx[k]];

                float dpx = pCur[k].x - pPrev[k].x, dmx = pN.x - pCur[k].x;
                float dpy = pCur[k].y - pPrev[k].y, dmy = pN.y - pCur[k].y;
                float dpz = pCur[k].z - pPrev[k].z, dmz = pN.z - pCur[k].z;
                float dpw = pCur[k].w - pPrev[k].w, dmw = pN.w - pCur[k].w;

                vA = fmaf(dpx, dpx, fmaf(dpy, dpy, fmaf(dpz, dpz, fmaf(dpw, dpw, vA))));
                vB = fmaf(dmx, dmx, fmaf(dmy, dmy, fmaf(dmz, dmz, fmaf(dmw, dmw, vB))));
                vC = fmaf(dpx, dmx, fmaf(dpy, dmy, fmaf(dpz, dmz, fmaf(dpw, dmw, vC))));
                vD = fmaf(fv.x, dpx, fmaf(fv.y, dpy, fmaf(fv.z, dpz, fmaf(fv.w, dpw, vD))));
                vE = fmaf(fv.x, dmx, fmaf(fv.y, dmy, fmaf(fv.z, dmz, fmaf(fv.w, dmw, vE))));
                vW = fmaf(fv.x, fv.x, fmaf(fv.y, fv.y, fmaf(fv.z, fv.z, fmaf(fv.w, fv.w, vW))));

                pPrev[k] = pCur[k];
                pCur[k]  = pN;
            }
        }

        float vals[6] = { vA, vB, vC, vD, vE, vW };
        #pragma unroll
        for (int c = 0; c < 6; c++) {
            float r = warpSum(vals[c]);
            if ((t & 31) == 0) sred[c][t >> 5] = r;
        }
        __syncthreads();
        if (t < 6) {
            float s = 0.f;
            #pragma unroll
            for (int w = 0; w < TA / 32; w++) s += sred[t][w];
            g_part[((size_t)ii * nb + b) * 6 + t] = s;
        }
        __syncthreads();
    }
}

__global__ void nebScalars(const float* __restrict__ eng, int n_img, int nb)
{
    const int j = blockIdx.x;
    const int t = threadIdx.x;

    float acc[6] = {0.f, 0.f, 0.f, 0.f, 0.f, 0.f};
    for (int b = t; b < nb; b += blockDim.x) {
        #pragma unroll
        for (int c = 0; c < 6; c++)
            acc[c] += g_part[((size_t)j * nb + b) * 6 + c];
    }

    __shared__ float sred[6][8];
    #pragma unroll
    for (int c = 0; c < 6; c++) {
        float r = warpSum(acc[c]);
        if ((t & 31) == 0) sred[c][t >> 5] = r;
    }
    __syncthreads();

    if (t == 0) {
        float S[6];
        #pragma unroll
        for (int c = 0; c < 6; c++) {
            float s = 0.f;
            #pragma unroll
            for (int w = 0; w < 8; w++) s += sred[c][w];
            S[c] = s;
        }
        float g1, al, be;
        coefFrom(S, j, g1, al, be);
        g_coef[j * 4 + 0] = g1;
        g_coef[j * 4 + 1] = al;
        g_coef[j * 4 + 2] = be;
    }
}

__global__ void nebOut(
    const float4* __restrict__ pos4,
    const float4* __restrict__ frc4,
    float4* __restrict__ out4,
    int nvec, int n_img)
{
    size_t gid = (size_t)blockIdx.x * blockDim.x + threadIdx.x;
    size_t total = (size_t)n_img * nvec;
    if (gid >= total) return;

    int img = (int)(gid / (unsigned)nvec);
    float4 f = frc4[gid];

    if (img == 0 || img == n_img - 1) { out4[gid] = f; return; }

    const int ii = img - 1;
    const float g1 = __ldg(&g_coef[ii * 4 + 0]);
    const float al = __ldg(&g_coef[ii * 4 + 1]);
    const float be = __ldg(&g_coef[ii * 4 + 2]);

    float4 pm = pos4[gid - nvec];
    float4 pc = pos4[gid];
    float4 pp = pos4[gid + nvec];

    float4 o;
    o.x = fmaf(g1, f.x, fmaf(al, pc.x - pm.x, be * (pp.x - pc.x)));
    o.y = fmaf(g1, f.y, fmaf(al, pc.y - pm.y, be * (pp.y - pc.y)));
    o.z = fmaf(g1, f.z, fmaf(al, pc.z - pm.z, be * (pp.z - pc.z)));
    o.w = fmaf(g1, f.w, fmaf(al, pc.w - pm.w, be * (pp.w - pc.w)));
    out4[gid] = o;
}

// =============================================================================
extern "C" void kernel_launch(void* const* d_in, const int* in_sizes, int n_in,
                              void* d_out, int out_size)
{
    const float* pos = (const float*)d_in[0];
    const float* frc = (const float*)d_in[1];
    const float* eng = (const float*)d_in[2];

    const int n_img    = in_sizes[2];
    const long per_img = (long)in_sizes[0] / n_img;
    const int  nvec    = (int)(per_img / 4);
    const int  n_int   = n_img - 2;

    const float4* pos4 = (const float4*)pos;
    const float4* frc4 = (const float4*)frc;
    float4* out4 = (float4*)d_out;

    const int G = (nvec + TF * KPTF - 1) / (TF * KPTF);

    // deadlock safety: persistent grid must be fully co-resident
    int dev = 0;
    cudaGetDevice(&dev);
    int numSM = 0;
    cudaDeviceGetAttribute(&numSM, cudaDevAttrMultiProcessorCount, dev);
    int maxB = 0;
    cudaOccupancyMaxActiveBlocksPerMultiprocessor(&maxB, nebFused, TF, 0);

    if (n_int >= 1 && n_int <= MAX_INT && G <= MAX_G &&
        (long)maxB * numSM >= G) {
        nebInit<<<1, 32>>>(eng, n_img);
        nebFused<<<G, TF>>>(pos4, frc4, out4, nvec, n_img, G);
    } else {
        const int nb = (nvec + TA * KPT - 1) / (TA * KPT);
        nebReduce<<<nb, TA>>>(pos4, frc4, nvec, n_img, nb);
        nebScalars<<<n_int, 256>>>(eng, n_img, nb);
        size_t total = (size_t)n_img * nvec;
        int blocksC = (int)((total + 255) / 256);
        nebOut<<<blocksC, 256>>>(pos4, frc4, out4, nvec, n_img);
    }
}